// round 4
// baseline (speedup 1.0000x reference)
#include <cuda_runtime.h>
#include <cfloat>

// ---------------------------------------------------------------------------
// PillarMaxPooling: h = relu((x @ W) * bn_scale + bn_shift); segment_max -> M
//   k1: scatter-COPY point feature rows into pillar buckets (48B padded rows).
//       Coalesced reads of gf; 3 aligned vector stores per point.
//   k2: warp-per-pillar. Pillar block is CONTIGUOUS -> coalesced uint4 copy to
//       SMEM, then point-pair f32x2 FMA mainloop (register pair-packing).
//       FMA pipe at its 10-fma2/pt floor; no random gather, no scatter STS.
// ---------------------------------------------------------------------------

#define CAP      64
#define MAXM     262144
#define OVFCAP   65536
#define BN_EPS   1e-3f
#define K2_THREADS 256
#define K2_WARPS   8
#define ROWF     12            // floats per bucket row (48B, 16B-aligned slots)

__device__ int   d_count[MAXM];                              // zero-init, k2 re-zeroes
__device__ __align__(16) float d_bucketF[(size_t)MAXM * CAP * ROWF];
__device__ int   d_ovflist[OVFCAP];
__device__ int   d_ovfcnt;                                   // zero-init, k2 re-zeroes

typedef unsigned long long u64;

__device__ __forceinline__ u64 pk2(float x, float y) {
    u64 r; asm("mov.b64 %0, {%1, %2};" : "=l"(r) : "f"(x), "f"(y)); return r;
}
__device__ __forceinline__ void upk2(u64 v, float& x, float& y) {
    asm("mov.b64 {%0, %1}, %2;" : "=f"(x), "=f"(y) : "l"(v));
}
__device__ __forceinline__ u64 fma2(u64 a, u64 b, u64 c) {
    u64 d; asm("fma.rn.f32x2 %0, %1, %2, %3;" : "=l"(d) : "l"(a), "l"(b), "l"(c)); return d;
}
__device__ __forceinline__ u64 mul2(u64 a, u64 b) {
    u64 d; asm("mul.rn.f32x2 %0, %1, %2;" : "=l"(d) : "l"(a), "l"(b)); return d;
}

// K1: thread per point. Coalesced gf read, bucket slot via atomic, 3 vector stores.
__global__ void k1_scatter_copy(const float* __restrict__ gf,
                                const int* __restrict__ idx, int P) {
    int p = blockIdx.x * blockDim.x + threadIdx.x;
    if (p >= P) return;
    int i = idx[p];
    int s = atomicAdd(&d_count[i], 1);
    const float2* src = reinterpret_cast<const float2*>(gf + (size_t)p * 10);
    float2 v0 = src[0], v1 = src[1], v2 = src[2], v3 = src[3], v4 = src[4];
    if (s < CAP) {
        float* dst = d_bucketF + ((size_t)i * CAP + s) * ROWF;
        reinterpret_cast<float4*>(dst)[0] = make_float4(v0.x, v0.y, v1.x, v1.y);
        reinterpret_cast<float4*>(dst)[1] = make_float4(v2.x, v2.y, v3.x, v3.y);
        *reinterpret_cast<float2*>(dst + 8) = v4;
    } else {
        int o = atomicAdd(&d_ovfcnt, 1);
        if (o < OVFCAP) d_ovflist[o] = p;
        else atomicSub(&d_ovfcnt, 1);
    }
}

// K2: warp per pillar. Lane owns channels (2l, 2l+1).
__global__ void __launch_bounds__(K2_THREADS, 3)
k2_compute(const float* __restrict__ W,
           const float* __restrict__ gamma, const float* __restrict__ beta,
           const float* __restrict__ mean,  const float* __restrict__ var,
           const float* __restrict__ gf,    const int* __restrict__ idx,
           float* __restrict__ out, int M) {
    __shared__ __align__(16) float sm[K2_WARPS][32 * ROWF];  // 1536B per warp

    int lane = threadIdx.x & 31;
    int wloc = threadIdx.x >> 5;
    float* smw = sm[wloc];

    int gwarp = (blockIdx.x * K2_THREADS + threadIdx.x) >> 5;
    int nwarp = (gridDim.x * K2_THREADS) >> 5;

    int c0 = 2 * lane, c1 = 2 * lane + 1;
    float s0 = gamma[c0] * rsqrtf(var[c0] + BN_EPS);
    float s1 = gamma[c1] * rsqrtf(var[c1] + BN_EPS);
    float b0 = beta[c0] - mean[c0] * s0;
    float b1 = beta[c1] - mean[c1] * s1;

    u64 wA[10], wB[10];                       // splatted, scale-folded weights
#pragma unroll
    for (int k = 0; k < 10; k++) {
        float a = W[k * 64 + c0] * s0;
        float b = W[k * 64 + c1] * s1;
        wA[k] = pk2(a, a);
        wB[k] = pk2(b, b);
    }

    for (int i = gwarp; i < M; i += nwarp) {
        int n  = d_count[i];
        int nc = n < CAP ? n : CAP;
        float mA = -FLT_MAX, mB = -FLT_MAX;
        const float* gbase = d_bucketF + (size_t)i * CAP * ROWF;

        for (int base = 0; base < nc; base += 32) {
            int m = nc - base; if (m > 32) m = 32;
            __syncwarp();
            // coalesced block copy: m rows x 48B
            {
                const uint4* g4 = reinterpret_cast<const uint4*>(gbase + base * ROWF);
                uint4* s4 = reinterpret_cast<uint4*>(smw);
                int nu = m * 3;
                if (lane      < nu) s4[lane]      = g4[lane];
                if (lane + 32 < nu) s4[lane + 32] = g4[lane + 32];
                if (lane + 64 < nu) s4[lane + 64] = g4[lane + 64];
            }
            __syncwarp();

            int pairs = (m + 1) >> 1;
#pragma unroll 2
            for (int pr = 0; pr < pairs; pr++) {
                const float* pa = smw + pr * (2 * ROWF);
                const float* pb = (2 * pr + 1 < m) ? pa + ROWF : pa;  // odd: self-pair
                float4 A0 = *reinterpret_cast<const float4*>(pa);
                float4 B0 = *reinterpret_cast<const float4*>(pb);
                u64 f0 = pk2(A0.x, B0.x), f1 = pk2(A0.y, B0.y);
                u64 f2 = pk2(A0.z, B0.z), f3 = pk2(A0.w, B0.w);
                u64 aA = mul2(f0, wA[0]);
                u64 aB = mul2(f0, wB[0]);
                aA = fma2(f1, wA[1], aA);  aB = fma2(f1, wB[1], aB);
                aA = fma2(f2, wA[2], aA);  aB = fma2(f2, wB[2], aB);
                aA = fma2(f3, wA[3], aA);  aB = fma2(f3, wB[3], aB);
                float4 A1 = *reinterpret_cast<const float4*>(pa + 4);
                float4 B1 = *reinterpret_cast<const float4*>(pb + 4);
                u64 f4 = pk2(A1.x, B1.x), f5 = pk2(A1.y, B1.y);
                u64 f6 = pk2(A1.z, B1.z), f7 = pk2(A1.w, B1.w);
                aA = fma2(f4, wA[4], aA);  aB = fma2(f4, wB[4], aB);
                aA = fma2(f5, wA[5], aA);  aB = fma2(f5, wB[5], aB);
                aA = fma2(f6, wA[6], aA);  aB = fma2(f6, wB[6], aB);
                aA = fma2(f7, wA[7], aA);  aB = fma2(f7, wB[7], aB);
                float2 A2 = *reinterpret_cast<const float2*>(pa + 8);
                float2 B2 = *reinterpret_cast<const float2*>(pb + 8);
                u64 f8 = pk2(A2.x, B2.x), f9 = pk2(A2.y, B2.y);
                aA = fma2(f8, wA[8], aA);  aB = fma2(f8, wB[8], aB);
                aA = fma2(f9, wA[9], aA);  aB = fma2(f9, wB[9], aB);
                float xa, xb, ya, yb;
                upk2(aA, xa, xb);
                upk2(aB, ya, yb);
                mA = fmaxf(fmaxf(mA, xa), xb);
                mB = fmaxf(fmaxf(mB, ya), yb);
            }
        }

        // inline overflow handling (statistically never taken)
        if (n > CAP) {
            int V = d_ovfcnt; if (V > OVFCAP) V = OVFCAP;
            int mine = 0;
            for (int e = 0; e < V; e++) {
                int pid = d_ovflist[e];
                if (idx[pid] == i) {
                    mine++;
                    u64 aA = pk2(0.f, 0.f), aB = aA;
#pragma unroll
                    for (int k = 0; k < 10; k++) {
                        float f = gf[(size_t)pid * 10 + k];
                        u64 ff = pk2(f, f);
                        aA = fma2(ff, wA[k], aA);
                        aB = fma2(ff, wB[k], aB);
                    }
                    float xa, t0, ya, t1;
                    upk2(aA, xa, t0); upk2(aB, ya, t1);
                    mA = fmaxf(mA, xa);
                    mB = fmaxf(mB, ya);
                }
            }
            if (lane == 0 && mine) atomicSub(&d_ovfcnt, mine);
        }

        if (lane == 0) d_count[i] = 0;        // self-reset for graph replay

        float r0 = 0.0f, r1 = 0.0f;
        if (n > 0) {
            r0 = fmaxf(mA + b0, 0.0f);
            r1 = fmaxf(mB + b1, 0.0f);
        }
        *reinterpret_cast<float2*>(out + (size_t)i * 64 + c0) = make_float2(r0, r1);
    }
}

extern "C" void kernel_launch(void* const* d_in, const int* in_sizes, int n_in,
                              void* d_out, int out_size) {
    const float* gf    = (const float*)d_in[0];
    const int*   idx   = (const int*)  d_in[1];
    const float* W     = (const float*)d_in[3];
    const float* gamma = (const float*)d_in[4];
    const float* beta  = (const float*)d_in[5];
    const float* mean  = (const float*)d_in[6];
    const float* var   = (const float*)d_in[7];
    float*       out   = (float*)d_out;

    int P = in_sizes[1];
    int M = out_size / 64;

    int g1 = (P + 255) / 256;
    k1_scatter_copy<<<g1, 256>>>(gf, idx, P);
    k2_compute<<<444, K2_THREADS>>>(W, gamma, beta, mean, var, gf, idx, out, M);
}

// round 5
// speedup vs baseline: 1.4739x; 1.4739x over previous
#include <cuda_runtime.h>
#include <cfloat>

// ---------------------------------------------------------------------------
// PillarMaxPooling: h = relu((x @ W) * bn_scale + bn_shift); segment_max -> M
//   k1: counting-bucket scatter of point IDS (int4-vectorized index read)
//   k2: warp-per-pillar. Gather uses 4 LANES PER POINT (one LDG.64 instruction
//       covers bytes [0,32) of 8 rows -> ~1 wavefront/pt instead of 5), lanes
//       write directly into pair-packed SMEM; mainloop is R2's f32x2 FMA with
//       LDS.128 landing on operand pairs (no packing MOVs).
// ---------------------------------------------------------------------------

#define CAP      64
#define MAXM     262144
#define OVFCAP   65536
#define BN_EPS   1e-3f
#define K2_THREADS 256
#define K2_WARPS   8

__device__ int   d_count[MAXM];                 // zero-init, k2 re-zeroes
__device__ int   d_bucket[(size_t)MAXM * CAP];
__device__ int   d_ovflist[OVFCAP];
__device__ int   d_ovfcnt;                      // zero-init

typedef unsigned long long u64;

__device__ __forceinline__ u64 pk2(float x, float y) {
    u64 r; asm("mov.b64 %0, {%1, %2};" : "=l"(r) : "f"(x), "f"(y)); return r;
}
__device__ __forceinline__ void upk2(u64 v, float& x, float& y) {
    asm("mov.b64 {%0, %1}, %2;" : "=f"(x), "=f"(y) : "l"(v));
}
__device__ __forceinline__ u64 fma2(u64 a, u64 b, u64 c) {
    u64 d; asm("fma.rn.f32x2 %0, %1, %2, %3;" : "=l"(d) : "l"(a), "l"(b), "l"(c)); return d;
}
__device__ __forceinline__ u64 mul2(u64 a, u64 b) {
    u64 d; asm("mul.rn.f32x2 %0, %1, %2;" : "=l"(d) : "l"(a), "l"(b)); return d;
}

__device__ __forceinline__ void put_point(int i, int p) {
    int s = atomicAdd(&d_count[i], 1);
    if (s < CAP) {
        d_bucket[(size_t)i * CAP + s] = p;
    } else {
        int o = atomicAdd(&d_ovfcnt, 1);
        if (o < OVFCAP) d_ovflist[o] = p;
        else atomicSub(&d_ovfcnt, 1);
    }
}

// K1: bucket the point ids per pillar.
__global__ void k1_scatter(const int* __restrict__ idx, int P) {
    int t  = blockIdx.x * blockDim.x + threadIdx.x;
    int p0 = t * 4;
    if (p0 + 3 < P) {
        int4 v = *reinterpret_cast<const int4*>(idx + p0);
        put_point(v.x, p0);
        put_point(v.y, p0 + 1);
        put_point(v.z, p0 + 2);
        put_point(v.w, p0 + 3);
    } else {
        for (int p = p0; p < P; p++) put_point(idx[p], p);
    }
}

// K2: warp per pillar. Lane owns channels (2l, 2l+1). Chunks of 16 points;
// SMEM pair-packed: word (slot*20 + 2k + par) = feature k of point 2*slot+par.
__global__ void __launch_bounds__(K2_THREADS)
k2_compute(const float* __restrict__ gf, const float* __restrict__ W,
           const float* __restrict__ gamma, const float* __restrict__ beta,
           const float* __restrict__ mean,  const float* __restrict__ var,
           const int* __restrict__ idx, float* __restrict__ out, int M) {
    __shared__ __align__(16) float sm[K2_WARPS][8 * 20];   // 8 pairs x 20 words

    int lane = threadIdx.x & 31;
    int wloc = threadIdx.x >> 5;
    float* smw = sm[wloc];

    int gwarp = (blockIdx.x * K2_THREADS + threadIdx.x) >> 5;
    int nwarp = (gridDim.x * K2_THREADS) >> 5;

    int cA = 2 * lane, cB = 2 * lane + 1;
    float sA = gamma[cA] * rsqrtf(var[cA] + BN_EPS);
    float sB = gamma[cB] * rsqrtf(var[cB] + BN_EPS);
    float bA = beta[cA] - mean[cA] * sA;
    float bB = beta[cB] - mean[cB] * sB;

    u64 wA[10], wB[10];                        // splatted, scale-folded weights
#pragma unroll
    for (int k = 0; k < 10; k++) {
        float a = W[k * 64 + cA] * sA;
        float b = W[k * 64 + cB] * sB;
        wA[k] = pk2(a, a);
        wB[k] = pk2(b, b);
    }

    int j4 = lane >> 2;    // point-in-group 0..7
    int c4 = lane & 3;     // float2 chunk 0..3

    for (int i = gwarp; i < M; i += nwarp) {
        int n  = d_count[i];
        int nc = n < CAP ? n : CAP;
        float mA = -FLT_MAX, mB = -FLT_MAX;

        for (int base = 0; base < nc; base += 16) {
            int m = nc - base; if (m > 16) m = 16;
            __syncwarp();
#pragma unroll
            for (int g = 0; g < 2; g++) {
                int t = 8 * g + j4;
                if (t < m) {
                    int pid = d_bucket[(size_t)i * CAP + base + t];
                    const float* row = gf + (size_t)pid * 10;
                    float2 v = *reinterpret_cast<const float2*>(row + 2 * c4);
                    float* s = smw + (t >> 1) * 20 + (t & 1);
                    s[4 * c4]     = v.x;
                    s[4 * c4 + 2] = v.y;
                    if (c4 == 0) {
                        float2 e = *reinterpret_cast<const float2*>(row + 8);
                        s[16] = e.x;
                        s[18] = e.y;
                    }
                }
            }
            __syncwarp();

            int  pairs = (m + 1) >> 1;
            bool odd   = (m & 1) != 0;
#pragma unroll 2
            for (int pr = 0; pr < pairs; pr++) {
                const ulonglong2* q = reinterpret_cast<const ulonglong2*>(smw + pr * 20);
                ulonglong2 q0 = q[0], q1 = q[1], q2 = q[2], q3 = q[3], q4 = q[4];
                u64 a = mul2(q0.x, wA[0]);
                u64 b = mul2(q0.x, wB[0]);
                a = fma2(q0.y, wA[1], a);  b = fma2(q0.y, wB[1], b);
                a = fma2(q1.x, wA[2], a);  b = fma2(q1.x, wB[2], b);
                a = fma2(q1.y, wA[3], a);  b = fma2(q1.y, wB[3], b);
                a = fma2(q2.x, wA[4], a);  b = fma2(q2.x, wB[4], b);
                a = fma2(q2.y, wA[5], a);  b = fma2(q2.y, wB[5], b);
                a = fma2(q3.x, wA[6], a);  b = fma2(q3.x, wB[6], b);
                a = fma2(q3.y, wA[7], a);  b = fma2(q3.y, wB[7], b);
                a = fma2(q4.x, wA[8], a);  b = fma2(q4.x, wB[8], b);
                a = fma2(q4.y, wA[9], a);  b = fma2(q4.y, wB[9], b);
                float xe, xo, ye, yo;
                upk2(a, xe, xo);
                upk2(b, ye, yo);
                if (odd && pr == pairs - 1) { xo = -FLT_MAX; yo = -FLT_MAX; }
                mA = fmaxf(fmaxf(mA, xe), xo);
                mB = fmaxf(fmaxf(mB, ye), yo);
            }
        }

        // inline overflow handling (statistically never taken)
        if (n > CAP) {
            int V = d_ovfcnt; if (V > OVFCAP) V = OVFCAP;
            int mine = 0;
            for (int e = 0; e < V; e++) {
                int pid = d_ovflist[e];
                if (idx[pid] == i) {
                    mine++;
                    u64 a = pk2(0.f, 0.f), b = a;
#pragma unroll
                    for (int k = 0; k < 10; k++) {
                        float f = gf[(size_t)pid * 10 + k];
                        u64 ff = pk2(f, f);
                        a = fma2(ff, wA[k], a);
                        b = fma2(ff, wB[k], b);
                    }
                    float xa, t0, ya, t1;
                    upk2(a, xa, t0); upk2(b, ya, t1);
                    mA = fmaxf(mA, xa);
                    mB = fmaxf(mB, ya);
                }
            }
            if (lane == 0 && mine) atomicSub(&d_ovfcnt, mine);
        }

        if (lane == 0) d_count[i] = 0;          // self-reset for graph replay

        float r0 = 0.0f, r1 = 0.0f;
        if (n > 0) {
            r0 = fmaxf(mA + bA, 0.0f);
            r1 = fmaxf(mB + bB, 0.0f);
        }
        *reinterpret_cast<float2*>(out + (size_t)i * 64 + cA) = make_float2(r0, r1);
    }
}

extern "C" void kernel_launch(void* const* d_in, const int* in_sizes, int n_in,
                              void* d_out, int out_size) {
    const float* gf    = (const float*)d_in[0];
    const int*   idx   = (const int*)  d_in[1];
    const float* W     = (const float*)d_in[3];
    const float* gamma = (const float*)d_in[4];
    const float* beta  = (const float*)d_in[5];
    const float* mean  = (const float*)d_in[6];
    const float* var   = (const float*)d_in[7];
    float*       out   = (float*)d_out;

    int P = in_sizes[1];
    int M = out_size / 64;

    int g1 = (P / 4 + 255) / 256 + 1;
    k1_scatter<<<g1, 256>>>(idx, P);
    k2_compute<<<592, K2_THREADS>>>(gf, W, gamma, beta, mean, var, idx, out, M);
}

// round 7
// speedup vs baseline: 1.8968x; 1.2869x over previous
#include <cuda_runtime.h>
#include <cfloat>

// ---------------------------------------------------------------------------
// PillarMaxPooling: h = relu((x @ W) * bn_scale + bn_shift); segment_max -> M
//   k1: counting-bucket scatter of point IDS (int4-vectorized)
//   k2: warp-per-pillar, 3-stage SOFTWARE PIPELINE across pillars:
//       compute(i) from SMEM | rows(i+1) LDG in flight | ids(i+2) LDG | n(i+3)
//       Pair-packed SMEM double buffer (R6 bug fixed: 320 floats = 16 pairs);
//       f32x2 FMA mainloop (at its pipe floor).
// ---------------------------------------------------------------------------

#define CAP      64
#define MAXM     262144
#define OVFCAP   65536
#define BN_EPS   1e-3f
#define K2_THREADS 256
#define K2_WARPS   8
#define BUFW     320            // 16 pairs x 20 words (32 points)

__device__ int   d_count[MAXM];                 // zero-init, k2 re-zeroes
__device__ int   d_bucket[(size_t)MAXM * CAP];
__device__ int   d_ovflist[OVFCAP];
__device__ int   d_ovfcnt;                      // zero-init

typedef unsigned long long u64;

__device__ __forceinline__ u64 pk2(float x, float y) {
    u64 r; asm("mov.b64 %0, {%1, %2};" : "=l"(r) : "f"(x), "f"(y)); return r;
}
__device__ __forceinline__ void upk2(u64 v, float& x, float& y) {
    asm("mov.b64 {%0, %1}, %2;" : "=f"(x), "=f"(y) : "l"(v));
}
__device__ __forceinline__ u64 fma2(u64 a, u64 b, u64 c) {
    u64 d; asm("fma.rn.f32x2 %0, %1, %2, %3;" : "=l"(d) : "l"(a), "l"(b), "l"(c)); return d;
}
__device__ __forceinline__ u64 mul2(u64 a, u64 b) {
    u64 d; asm("mul.rn.f32x2 %0, %1, %2;" : "=l"(d) : "l"(a), "l"(b)); return d;
}

__device__ __forceinline__ void put_point(int i, int p) {
    int s = atomicAdd(&d_count[i], 1);
    if (s < CAP) {
        d_bucket[(unsigned)i * CAP + s] = p;
    } else {
        int o = atomicAdd(&d_ovfcnt, 1);
        if (o < OVFCAP) d_ovflist[o] = p;
        else atomicSub(&d_ovfcnt, 1);
    }
}

__global__ void k1_scatter(const int* __restrict__ idx, int P) {
    int t  = blockIdx.x * blockDim.x + threadIdx.x;
    int p0 = t * 4;
    if (p0 + 3 < P) {
        int4 v = *reinterpret_cast<const int4*>(idx + p0);
        put_point(v.x, p0);
        put_point(v.y, p0 + 1);
        put_point(v.z, p0 + 2);
        put_point(v.w, p0 + 3);
    } else {
        for (int p = p0; p < P; p++) put_point(idx[p], p);
    }
}

// Dot-product mainloop over a pair-packed SMEM buffer; accumulates max into mA/mB.
__device__ __forceinline__ void pair_mainloop(const float* buf, int m,
                                              const u64* wA, const u64* wB,
                                              float& mA, float& mB) {
    int  pairs = (m + 1) >> 1;
    bool odd   = (m & 1) != 0;
#pragma unroll 2
    for (int pr = 0; pr < pairs; pr++) {
        const ulonglong2* q = reinterpret_cast<const ulonglong2*>(buf + pr * 20);
        ulonglong2 q0 = q[0], q1 = q[1], q2 = q[2], q3 = q[3], q4 = q[4];
        u64 a = mul2(q0.x, wA[0]);
        u64 b = mul2(q0.x, wB[0]);
        a = fma2(q0.y, wA[1], a);  b = fma2(q0.y, wB[1], b);
        a = fma2(q1.x, wA[2], a);  b = fma2(q1.x, wB[2], b);
        a = fma2(q1.y, wA[3], a);  b = fma2(q1.y, wB[3], b);
        a = fma2(q2.x, wA[4], a);  b = fma2(q2.x, wB[4], b);
        a = fma2(q2.y, wA[5], a);  b = fma2(q2.y, wB[5], b);
        a = fma2(q3.x, wA[6], a);  b = fma2(q3.x, wB[6], b);
        a = fma2(q3.y, wA[7], a);  b = fma2(q3.y, wB[7], b);
        a = fma2(q4.x, wA[8], a);  b = fma2(q4.x, wB[8], b);
        a = fma2(q4.y, wA[9], a);  b = fma2(q4.y, wB[9], b);
        float xe, xo, ye, yo;
        upk2(a, xe, xo);
        upk2(b, ye, yo);
        if (odd && pr == pairs - 1) { xo = -FLT_MAX; yo = -FLT_MAX; }
        mA = fmaxf(fmaxf(mA, xe), xo);
        mB = fmaxf(fmaxf(mB, ye), yo);
    }
}

__global__ void __launch_bounds__(K2_THREADS)
k2_compute(const float* __restrict__ gf, const float* __restrict__ W,
           const float* __restrict__ gamma, const float* __restrict__ beta,
           const float* __restrict__ mean,  const float* __restrict__ var,
           const int* __restrict__ idx, float* __restrict__ out, int M) {
    __shared__ __align__(16) float sm[K2_WARPS][2][BUFW];   // 20 KB

    int lane = threadIdx.x & 31;
    int wloc = threadIdx.x >> 5;

    int gwarp = (blockIdx.x * K2_THREADS + threadIdx.x) >> 5;
    int nw    = (gridDim.x * K2_THREADS) >> 5;

    int cA = 2 * lane, cB = 2 * lane + 1;
    float sA = gamma[cA] * rsqrtf(var[cA] + BN_EPS);
    float sB = gamma[cB] * rsqrtf(var[cB] + BN_EPS);
    float bA = beta[cA] - mean[cA] * sA;
    float bB = beta[cB] - mean[cB] * sB;

    u64 wA[10], wB[10];
#pragma unroll
    for (int k = 0; k < 10; k++) {
        float a = W[k * 64 + cA] * sA;
        float b = W[k * 64 + cB] * sB;
        wA[k] = pk2(a, a);
        wB[k] = pk2(b, b);
    }

    // ---- pipeline prologue -------------------------------------------------
    int i0 = gwarp, i1 = i0 + nw, i2 = i1 + nw, i3 = i2 + nw;

    int n0 = (i0 < M) ? d_count[i0] : 0;
    int m0 = n0 < 32 ? n0 : 32;
    float r[10];
    if (i0 < M && lane < m0) {
        int pid = d_bucket[(unsigned)i0 * CAP + lane];
        const float2* row = reinterpret_cast<const float2*>(gf + (unsigned)pid * 10u);
        float2 v0 = row[0], v1 = row[1], v2 = row[2], v3 = row[3], v4 = row[4];
        r[0]=v0.x; r[1]=v0.y; r[2]=v1.x; r[3]=v1.y; r[4]=v2.x;
        r[5]=v2.y; r[6]=v3.x; r[7]=v3.y; r[8]=v4.x; r[9]=v4.y;
    }
    int n1  = (i1 < M) ? d_count[i1] : 0;
    int id1 = 0;
    if (i1 < M && lane < (n1 < 32 ? n1 : 32)) id1 = d_bucket[(unsigned)i1 * CAP + lane];
    int n2  = (i2 < M) ? d_count[i2] : 0;

    int cur = 0;
    // ---- pipelined main loop ------------------------------------------------
    while (i0 < M) {
        float* buf = sm[wloc][cur];

        // stage 1: deposit rows(i0) into SMEM (pair-packed, <= 16 pairs = 320 words)
        if (lane < m0) {
            float* s = buf + (lane >> 1) * 20 + (lane & 1);
#pragma unroll
            for (int k = 0; k < 10; k++) s[2 * k] = r[k];
        }
        // stage 2: issue rows(i1) LDGs (uses id1 from last iteration)
        int m1 = n1 < 32 ? n1 : 32;
        if (i1 < M && lane < m1) {
            const float2* row = reinterpret_cast<const float2*>(gf + (unsigned)id1 * 10u);
            float2 v0 = row[0], v1 = row[1], v2 = row[2], v3 = row[3], v4 = row[4];
            r[0]=v0.x; r[1]=v0.y; r[2]=v1.x; r[3]=v1.y; r[4]=v2.x;
            r[5]=v2.y; r[6]=v3.x; r[7]=v3.y; r[8]=v4.x; r[9]=v4.y;
        }
        // stage 3: issue ids(i2) LDG (uses n2 from last iteration)
        int id2 = 0;
        if (i2 < M && lane < (n2 < 32 ? n2 : 32)) id2 = d_bucket[(unsigned)i2 * CAP + lane];
        // stage 4: issue count(i3) LDG
        int n3 = (i3 < M) ? d_count[i3] : 0;

        __syncwarp();

        // compute pillar i0
        float mA = -FLT_MAX, mB = -FLT_MAX;
        pair_mainloop(buf, m0, wA, wB, mA, mB);

        // rare: extra chunks (32 < n <= CAP)
        if (n0 > 32) {
            int nc = n0 < CAP ? n0 : CAP;
            for (int base = 32; base < nc; base += 32) {
                int m = nc - base; if (m > 32) m = 32;
                __syncwarp();
                if (lane < m) {
                    int pid = d_bucket[(unsigned)i0 * CAP + base + lane];
                    const float2* row = reinterpret_cast<const float2*>(gf + (unsigned)pid * 10u);
                    float2 v0 = row[0], v1 = row[1], v2 = row[2], v3 = row[3], v4 = row[4];
                    float vv[10] = {v0.x,v0.y,v1.x,v1.y,v2.x,v2.y,v3.x,v3.y,v4.x,v4.y};
                    float* s = buf + (lane >> 1) * 20 + (lane & 1);
#pragma unroll
                    for (int k = 0; k < 10; k++) s[2 * k] = vv[k];
                }
                __syncwarp();
                pair_mainloop(buf, m, wA, wB, mA, mB);
            }
        }
        // rare: overflow (n > CAP)
        if (n0 > CAP) {
            int V = d_ovfcnt; if (V > OVFCAP) V = OVFCAP;
            int mine = 0;
            for (int e = 0; e < V; e++) {
                int pid = d_ovflist[e];
                if (idx[pid] == i0) {
                    mine++;
                    u64 a = pk2(0.f, 0.f), b = a;
#pragma unroll
                    for (int k = 0; k < 10; k++) {
                        float f = gf[(unsigned)pid * 10u + k];
                        u64 ff = pk2(f, f);
                        a = fma2(ff, wA[k], a);
                        b = fma2(ff, wB[k], b);
                    }
                    float xa, t0, ya, t1;
                    upk2(a, xa, t0); upk2(b, ya, t1);
                    mA = fmaxf(mA, xa);
                    mB = fmaxf(mB, ya);
                }
            }
            if (lane == 0 && mine) atomicSub(&d_ovfcnt, mine);
        }

        if (lane == 0 && n0 > 0) d_count[i0] = 0;   // self-reset for graph replay

        float o0 = 0.0f, o1 = 0.0f;
        if (n0 > 0) {
            o0 = fmaxf(mA + bA, 0.0f);
            o1 = fmaxf(mB + bB, 0.0f);
        }
        *reinterpret_cast<float2*>(out + (unsigned)i0 * 64 + cA) = make_float2(o0, o1);

        // pipeline shift
        i0 = i1; n0 = n1; m0 = m1;
        i1 = i2; n1 = n2; id1 = id2;
        i2 = i3; n2 = n3;
        i3 += nw;
        cur ^= 1;
    }
}

extern "C" void kernel_launch(void* const* d_in, const int* in_sizes, int n_in,
                              void* d_out, int out_size) {
    const float* gf    = (const float*)d_in[0];
    const int*   idx   = (const int*)  d_in[1];
    const float* W     = (const float*)d_in[3];
    const float* gamma = (const float*)d_in[4];
    const float* beta  = (const float*)d_in[5];
    const float* mean  = (const float*)d_in[6];
    const float* var   = (const float*)d_in[7];
    float*       out   = (float*)d_out;

    int P = in_sizes[1];
    int M = out_size / 64;

    int g1 = (P / 4 + 255) / 256 + 1;
    k1_scatter<<<g1, 256>>>(idx, P);
    k2_compute<<<592, K2_THREADS>>>(gf, W, gamma, beta, mean, var, idx, out, M);
}